// round 2
// baseline (speedup 1.0000x reference)
#include <cuda_runtime.h>
#include <math.h>

#define BATCH 8
#define NN    4096
#define EE    1024
#define CC    512

// ---- scratch (device globals: allocation-free) ----
__device__ float g_Q [(size_t)BATCH * NN * CC];        // 64 MB
__device__ float g_KV[(size_t)BATCH * EE * 2 * CC];    // 32 MB
__device__ float g_Vt[(size_t)BATCH * CC * EE];        // 16 MB  (V transposed: [b][c][e])
__device__ float g_S [(size_t)BATCH * NN * EE];        // 128 MB (attention logits / probs)

// ============================================================================
// Generic NT GEMM: C[m,n] = alpha * sum_k A[m,k]*B[n,k] + bias[n]
// Tile: BM=BN=128, BK=8, 256 threads, 8x8 per-thread register tile.
// All problem dims here are multiples of the tile — no bounds checks.
// ============================================================================
__global__ __launch_bounds__(256) void gemm_nt(
    const float* __restrict__ A, const float* __restrict__ B,
    const float* __restrict__ bias, float* __restrict__ C,
    int K, int lda, int ldb, int ldc,
    size_t sA, size_t sB, size_t sC, float alpha)
{
    __shared__ float As[8][128];
    __shared__ float Bs[8][128];

    A += (size_t)blockIdx.z * sA;
    B += (size_t)blockIdx.z * sB;
    C += (size_t)blockIdx.z * sC;

    const int bm = blockIdx.y * 128;
    const int bn = blockIdx.x * 128;
    const int tid  = threadIdx.x;
    const int lrow = tid >> 1;            // 0..127
    const int lcol = (tid & 1) << 2;      // 0 or 4
    const int ty   = tid >> 4;            // 0..15
    const int tx   = tid & 15;            // 0..15

    const float* Aptr = A + (size_t)(bm + lrow) * lda + lcol;
    const float* Bptr = B + (size_t)(bn + lrow) * ldb + lcol;

    float acc[8][8];
    #pragma unroll
    for (int i = 0; i < 8; i++)
        #pragma unroll
        for (int j = 0; j < 8; j++) acc[i][j] = 0.0f;

    for (int k0 = 0; k0 < K; k0 += 8) {
        float4 av = *(const float4*)(Aptr + k0);
        float4 bv = *(const float4*)(Bptr + k0);
        As[lcol + 0][lrow] = av.x;  As[lcol + 1][lrow] = av.y;
        As[lcol + 2][lrow] = av.z;  As[lcol + 3][lrow] = av.w;
        Bs[lcol + 0][lrow] = bv.x;  Bs[lcol + 1][lrow] = bv.y;
        Bs[lcol + 2][lrow] = bv.z;  Bs[lcol + 3][lrow] = bv.w;
        __syncthreads();

        #pragma unroll
        for (int kk = 0; kk < 8; kk++) {
            float af[8], bf[8];
            #pragma unroll
            for (int i = 0; i < 8; i++) af[i] = As[kk][ty * 8 + i];
            #pragma unroll
            for (int j = 0; j < 8; j++) bf[j] = Bs[kk][tx * 8 + j];
            #pragma unroll
            for (int i = 0; i < 8; i++)
                #pragma unroll
                for (int j = 0; j < 8; j++)
                    acc[i][j] = fmaf(af[i], bf[j], acc[i][j]);
        }
        __syncthreads();
    }

    #pragma unroll
    for (int i = 0; i < 8; i++) {
        size_t row = (size_t)(bm + ty * 8 + i);
        #pragma unroll
        for (int j = 0; j < 8; j += 4) {
            int col = bn + tx * 8 + j;
            float4 v;
            v.x = acc[i][j + 0] * alpha + (bias ? bias[col + 0] : 0.0f);
            v.y = acc[i][j + 1] * alpha + (bias ? bias[col + 1] : 0.0f);
            v.z = acc[i][j + 2] * alpha + (bias ? bias[col + 2] : 0.0f);
            v.w = acc[i][j + 3] * alpha + (bias ? bias[col + 3] : 0.0f);
            *(float4*)&C[row * ldc + col] = v;
        }
    }
}

// ============================================================================
// Transpose the V half of KV into Vt[b][c][e]  (so PV becomes NT-form GEMM)
// KV layout: [b*EE + e][2*CC], V = cols [CC, 2*CC)
// ============================================================================
__global__ void transpose_v(const float* __restrict__ KV, float* __restrict__ Vt)
{
    __shared__ float tile[32][33];
    const int b  = blockIdx.z;
    const int e0 = blockIdx.x * 32;
    const int c0 = blockIdx.y * 32;
    const int tx = threadIdx.x;   // 32
    const int ty = threadIdx.y;   // 8

    #pragma unroll
    for (int i = 0; i < 32; i += 8)
        tile[ty + i][tx] = KV[((size_t)b * EE + e0 + ty + i) * (2 * CC) + CC + c0 + tx];
    __syncthreads();
    #pragma unroll
    for (int i = 0; i < 32; i += 8)
        Vt[((size_t)b * CC + c0 + ty + i) * EE + e0 + tx] = tile[tx][ty + i];
}

// ============================================================================
// Row softmax over E=1024, one block (256 threads, float4 each) per row.
// ============================================================================
__global__ __launch_bounds__(256) void softmax_rows(float* __restrict__ S)
{
    __shared__ float red[32];
    const size_t row = blockIdx.x;
    float4* p = (float4*)(S + row * (size_t)EE);
    const int t = threadIdx.x;

    float4 v = p[t];

    // ---- block max ----
    float m = fmaxf(fmaxf(v.x, v.y), fmaxf(v.z, v.w));
    #pragma unroll
    for (int o = 16; o; o >>= 1) m = fmaxf(m, __shfl_xor_sync(0xffffffffu, m, o));
    if ((t & 31) == 0) red[t >> 5] = m;
    __syncthreads();
    if (t < 32) {
        float x = (t < 8) ? red[t] : -INFINITY;
        #pragma unroll
        for (int o = 4; o; o >>= 1) x = fmaxf(x, __shfl_xor_sync(0xffffffffu, x, o));
        if (t == 0) red[0] = x;
    }
    __syncthreads();
    m = red[0];
    __syncthreads();   // protect red[] before reuse

    // ---- exp + block sum ----
    v.x = __expf(v.x - m); v.y = __expf(v.y - m);
    v.z = __expf(v.z - m); v.w = __expf(v.w - m);
    float s = v.x + v.y + v.z + v.w;
    #pragma unroll
    for (int o = 16; o; o >>= 1) s += __shfl_xor_sync(0xffffffffu, s, o);
    if ((t & 31) == 0) red[t >> 5] = s;
    __syncthreads();
    if (t < 32) {
        float x = (t < 8) ? red[t] : 0.0f;
        #pragma unroll
        for (int o = 4; o; o >>= 1) x += __shfl_xor_sync(0xffffffffu, x, o);
        if (t == 0) red[0] = x;
    }
    __syncthreads();
    const float inv = 1.0f / red[0];

    v.x *= inv; v.y *= inv; v.z *= inv; v.w *= inv;
    p[t] = v;
}

// ============================================================================
// launch
// ============================================================================
extern "C" void kernel_launch(void* const* d_in, const int* in_sizes, int n_in,
                              void* d_out, int out_size)
{
    const float* node  = (const float*)d_in[0];   // (B,N,C)
    const float* hyper = (const float*)d_in[1];   // (B,E,C)
    const float* Wq    = (const float*)d_in[2];   // (C,C)
    const float* bq    = (const float*)d_in[3];   // (C,)
    const float* Wkv   = (const float*)d_in[4];   // (2C,C)
    const float* bkv   = (const float*)d_in[5];   // (2C,)
    float* out = (float*)d_out;                   // (B,N,C)

    float *pQ, *pKV, *pVt, *pS;
    cudaGetSymbolAddress((void**)&pQ,  g_Q);
    cudaGetSymbolAddress((void**)&pKV, g_KV);
    cudaGetSymbolAddress((void**)&pVt, g_Vt);
    cudaGetSymbolAddress((void**)&pS,  g_S);

    const float scale = 0.04419417382415922f;  // 512^-0.5

    // 1) Q = node @ Wq^T + bq           (M=32768, N=512, K=512)
    gemm_nt<<<dim3(CC / 128, (BATCH * NN) / 128, 1), 256>>>(
        node, Wq, bq, pQ, CC, CC, CC, CC, 0, 0, 0, 1.0f);

    // 2) KV = hyper @ Wkv^T + bkv       (M=8192, N=1024, K=512)
    gemm_nt<<<dim3((2 * CC) / 128, (BATCH * EE) / 128, 1), 256>>>(
        hyper, Wkv, bkv, pKV, CC, CC, CC, 2 * CC, 0, 0, 0, 1.0f);

    // 3) Vt[b][c][e] = V[b][e][c]
    transpose_v<<<dim3(EE / 32, CC / 32, BATCH), dim3(32, 8)>>>(pKV, pVt);

    // 4) S = scale * Q @ K^T   (batched; K rows are first CC cols of KV, ldb=2C)
    gemm_nt<<<dim3(EE / 128, NN / 128, BATCH), 256>>>(
        pQ, pKV, nullptr, pS,
        CC, CC, 2 * CC, EE,
        (size_t)NN * CC, (size_t)EE * 2 * CC, (size_t)NN * EE, scale);

    // 5) softmax rows
    softmax_rows<<<BATCH * NN, 256>>>(pS);

    // 6) out = P @ Vt^T        (batched; M=4096, N=512, K=1024)
    gemm_nt<<<dim3(CC / 128, NN / 128, BATCH), 256>>>(
        pS, pVt, nullptr, out,
        EE, EE, EE, CC,
        (size_t)NN * EE, (size_t)CC * EE, (size_t)NN * CC, 1.0f);
}

// round 4
// speedup vs baseline: 1.9866x; 1.9866x over previous
#include <cuda_runtime.h>
#include <cuda_bf16.h>
#include <math.h>
#include <stdint.h>

#define BATCH 8
#define NN    4096
#define EE    1024
#define CC    512

// ---- scratch (device globals: allocation-free) ----
__device__ float g_Q [(size_t)BATCH * NN * CC];        // 64 MB
__device__ float g_KV[(size_t)BATCH * EE * 2 * CC];    // 32 MB
__device__ float g_Vt[(size_t)BATCH * CC * EE];        // 16 MB
__device__ float g_S [(size_t)BATCH * NN * EE];        // 128 MB

// ============================================================================
// helpers
// ============================================================================
static __device__ __forceinline__ uint32_t smem_u32(const void* p) {
    uint32_t a;
    asm("{ .reg .u64 t; cvta.to.shared.u64 t, %1; cvt.u32.u64 %0, t; }" : "=r"(a) : "l"(p));
    return a;
}

static __device__ __forceinline__ void mma_bf16(float* d, const uint32_t* a, const uint32_t* b) {
    asm volatile(
        "mma.sync.aligned.m16n8k16.row.col.f32.bf16.bf16.f32 "
        "{%0,%1,%2,%3}, {%4,%5,%6,%7}, {%8,%9}, {%0,%1,%2,%3};"
        : "+f"(d[0]), "+f"(d[1]), "+f"(d[2]), "+f"(d[3])
        : "r"(a[0]), "r"(a[1]), "r"(a[2]), "r"(a[3]), "r"(b[0]), "r"(b[1]));
}

static __device__ __forceinline__ void ldsm4(uint32_t* r, uint32_t addr) {
    asm volatile("ldmatrix.sync.aligned.m8n8.x4.shared.b16 {%0,%1,%2,%3}, [%4];"
        : "=r"(r[0]), "=r"(r[1]), "=r"(r[2]), "=r"(r[3]) : "r"(addr));
}

// bf16 hi/lo split of a float4 into two packed 8-byte values
static __device__ __forceinline__ void cvt_split(float4 v, uint2& hi, uint2& lo) {
    __nv_bfloat16 hx = __float2bfloat16(v.x), hy = __float2bfloat16(v.y);
    __nv_bfloat16 hz = __float2bfloat16(v.z), hw = __float2bfloat16(v.w);
    __nv_bfloat16 lx = __float2bfloat16(v.x - __bfloat162float(hx));
    __nv_bfloat16 ly = __float2bfloat16(v.y - __bfloat162float(hy));
    __nv_bfloat16 lz = __float2bfloat16(v.z - __bfloat162float(hz));
    __nv_bfloat16 lw = __float2bfloat16(v.w - __bfloat162float(hw));
    __nv_bfloat162 h01; h01.x = hx; h01.y = hy;
    __nv_bfloat162 h23; h23.x = hz; h23.y = hw;
    __nv_bfloat162 l01; l01.x = lx; l01.y = ly;
    __nv_bfloat162 l23; l23.x = lz; l23.y = lw;
    hi.x = *reinterpret_cast<uint32_t*>(&h01);
    hi.y = *reinterpret_cast<uint32_t*>(&h23);
    lo.x = *reinterpret_cast<uint32_t*>(&l01);
    lo.y = *reinterpret_cast<uint32_t*>(&l23);
}

// ============================================================================
// Tensor-core NT GEMM via mma.sync (bf16 hi/lo 3-pass, fp32 accumulate):
//   C[m,n] = alpha * sum_k A[m,k]*B[n,k] + bias[n]
// Tile 128x128x32, 512 threads (16 warps, 4x4), warp tile 32x32.
// smem rows padded to 80B (64B of bf16 data + 16B) -> conflict-free ldmatrix.
// Dims must be multiples of 128 (M,N) and 32 (K).
// ============================================================================
#define ROWB 80   // bytes per smem row (32 bf16 + pad)

__global__ __launch_bounds__(512) void tc_gemm(
    const float* __restrict__ A, const float* __restrict__ B,
    const float* __restrict__ bias, float* __restrict__ C,
    int K, int lda, int ldb, int ldc,
    size_t sA, size_t sB, size_t sC, float alpha)
{
    __shared__ __align__(16) unsigned char sm[4 * 128 * ROWB];   // 40 KB
    const uint32_t sAhi = smem_u32(sm);
    const uint32_t sAlo = sAhi + 128 * ROWB;
    const uint32_t sBhi = sAhi + 2 * 128 * ROWB;
    const uint32_t sBlo = sAhi + 3 * 128 * ROWB;

    A += (size_t)blockIdx.z * sA;
    B += (size_t)blockIdx.z * sB;
    C += (size_t)blockIdx.z * sC;
    const int bm = blockIdx.y * 128;
    const int bn = blockIdx.x * 128;

    const int tid  = threadIdx.x;
    const int wid  = tid >> 5;
    const int lane = tid & 31;
    const int warp_m = (wid >> 2) * 32;      // 0,32,64,96
    const int warp_n = (wid & 3) * 32;

    // gmem load mapping: 8 threads per row (32 floats), 64 rows per pass
    const int lrow = tid >> 3;               // 0..63
    const int lc4  = (tid & 7) * 4;          // float4 col
    const float* Aptr = A + (size_t)bm * lda + lc4;
    const float* Bptr = B + (size_t)bn * ldb + lc4;
    const uint32_t s_off = (uint32_t)((tid & 7) * 8);   // byte offset within row

    // ldmatrix per-lane addressing: row = base + (lane&15), k-half = lane>>4
    const uint32_t lm_row = (uint32_t)(lane & 15);
    const uint32_t lm_koff = (uint32_t)((lane >> 4) * 16);  // bytes (8 bf16)

    float acc[2][4][4];
    #pragma unroll
    for (int i = 0; i < 2; i++)
        #pragma unroll
        for (int j = 0; j < 4; j++)
            #pragma unroll
            for (int q = 0; q < 4; q++) acc[i][j][q] = 0.0f;

    for (int k0 = 0; k0 < K; k0 += 32) {
        // ---- load fp32 chunk into regs (overlaps with prior compute drain) ----
        float4 av0 = *(const float4*)(Aptr + (size_t)lrow * lda + k0);
        float4 av1 = *(const float4*)(Aptr + (size_t)(lrow + 64) * lda + k0);
        float4 bv0 = *(const float4*)(Bptr + (size_t)lrow * ldb + k0);
        float4 bv1 = *(const float4*)(Bptr + (size_t)(lrow + 64) * ldb + k0);

        __syncthreads();   // prior chunk's consumers done with smem

        uint2 h, l;
        cvt_split(av0, h, l);
        *(uint2*)(sm + (sAhi - sAhi) + lrow * ROWB + s_off) = h;                 // Ahi r0
        *(uint2*)(sm + 128 * ROWB + lrow * ROWB + s_off) = l;                    // Alo r0
        cvt_split(av1, h, l);
        *(uint2*)(sm + (lrow + 64) * ROWB + s_off) = h;
        *(uint2*)(sm + 128 * ROWB + (lrow + 64) * ROWB + s_off) = l;
        cvt_split(bv0, h, l);
        *(uint2*)(sm + 2 * 128 * ROWB + lrow * ROWB + s_off) = h;
        *(uint2*)(sm + 3 * 128 * ROWB + lrow * ROWB + s_off) = l;
        cvt_split(bv1, h, l);
        *(uint2*)(sm + 2 * 128 * ROWB + (lrow + 64) * ROWB + s_off) = h;
        *(uint2*)(sm + 3 * 128 * ROWB + (lrow + 64) * ROWB + s_off) = l;

        __syncthreads();

        // ---- compute: 2 k-steps of 16 ----
        #pragma unroll
        for (int ks = 0; ks < 2; ks++) {
            const uint32_t kb = (uint32_t)(ks * 32) + lm_koff;   // byte offset in row

            uint32_t aHi[2][4], aLo[2][4];
            #pragma unroll
            for (int am = 0; am < 2; am++) {
                const uint32_t ro = (uint32_t)(warp_m + am * 16) + lm_row;
                ldsm4(aHi[am], sAhi + ro * ROWB + kb);
                ldsm4(aLo[am], sAlo + ro * ROWB + kb);
            }
            uint32_t bHi[4][2], bLo[4][2];
            #pragma unroll
            for (int bg = 0; bg < 2; bg++) {
                const uint32_t ro = (uint32_t)(warp_n + bg * 16) + lm_row;
                uint32_t r[4];
                ldsm4(r, sBhi + ro * ROWB + kb);
                bHi[bg * 2 + 0][0] = r[0]; bHi[bg * 2 + 0][1] = r[2];
                bHi[bg * 2 + 1][0] = r[1]; bHi[bg * 2 + 1][1] = r[3];
                ldsm4(r, sBlo + ro * ROWB + kb);
                bLo[bg * 2 + 0][0] = r[0]; bLo[bg * 2 + 0][1] = r[2];
                bLo[bg * 2 + 1][0] = r[1]; bLo[bg * 2 + 1][1] = r[3];
            }
            #pragma unroll
            for (int am = 0; am < 2; am++)
                #pragma unroll
                for (int an = 0; an < 4; an++) {
                    mma_bf16(acc[am][an], aHi[am], bHi[an]);
                    mma_bf16(acc[am][an], aHi[am], bLo[an]);
                    mma_bf16(acc[am][an], aLo[am], bHi[an]);
                }
        }
    }

    // ---- epilogue: regs -> gmem, alpha & bias ----
    const bool hb = (bias != nullptr);
    #pragma unroll
    for (int am = 0; am < 2; am++) {
        #pragma unroll
        for (int an = 0; an < 4; an++) {
            const int col = bn + warp_n + an * 8 + (lane & 3) * 2;
            float bx = 0.f, by = 0.f;
            if (hb) { bx = __ldg(&bias[col]); by = __ldg(&bias[col + 1]); }
            const int r0 = bm + warp_m + am * 16 + (lane >> 2);
            float2 v0, v1;
            v0.x = acc[am][an][0] * alpha + bx;
            v0.y = acc[am][an][1] * alpha + by;
            v1.x = acc[am][an][2] * alpha + bx;
            v1.y = acc[am][an][3] * alpha + by;
            *(float2*)&C[(size_t)r0 * ldc + col]       = v0;
            *(float2*)&C[(size_t)(r0 + 8) * ldc + col] = v1;
        }
    }
}

// ============================================================================
// Transpose V half of KV into Vt[b][c][e]
// ============================================================================
__global__ void transpose_v(const float* __restrict__ KV, float* __restrict__ Vt)
{
    __shared__ float tile[32][33];
    const int b  = blockIdx.z;
    const int e0 = blockIdx.x * 32;
    const int c0 = blockIdx.y * 32;
    const int tx = threadIdx.x;
    const int ty = threadIdx.y;

    #pragma unroll
    for (int i = 0; i < 32; i += 8)
        tile[ty + i][tx] = KV[((size_t)b * EE + e0 + ty + i) * (2 * CC) + CC + c0 + tx];
    __syncthreads();
    #pragma unroll
    for (int i = 0; i < 32; i += 8)
        Vt[((size_t)b * CC + c0 + ty + i) * EE + e0 + tx] = tile[tx][ty + i];
}

// ============================================================================
// Row softmax over E=1024, one block per row.
// ============================================================================
__global__ __launch_bounds__(256) void softmax_rows(float* __restrict__ S)
{
    __shared__ float red[32];
    const size_t row = blockIdx.x;
    float4* p = (float4*)(S + row * (size_t)EE);
    const int t = threadIdx.x;

    float4 v = p[t];

    float m = fmaxf(fmaxf(v.x, v.y), fmaxf(v.z, v.w));
    #pragma unroll
    for (int o = 16; o; o >>= 1) m = fmaxf(m, __shfl_xor_sync(0xffffffffu, m, o));
    if ((t & 31) == 0) red[t >> 5] = m;
    __syncthreads();
    if (t < 32) {
        float x = (t < 8) ? red[t] : -INFINITY;
        #pragma unroll
        for (int o = 4; o; o >>= 1) x = fmaxf(x, __shfl_xor_sync(0xffffffffu, x, o));
        if (t == 0) red[0] = x;
    }
    __syncthreads();
    m = red[0];
    __syncthreads();

    v.x = __expf(v.x - m); v.y = __expf(v.y - m);
    v.z = __expf(v.z - m); v.w = __expf(v.w - m);
    float s = v.x + v.y + v.z + v.w;
    #pragma unroll
    for (int o = 16; o; o >>= 1) s += __shfl_xor_sync(0xffffffffu, s, o);
    if ((t & 31) == 0) red[t >> 5] = s;
    __syncthreads();
    if (t < 32) {
        float x = (t < 8) ? red[t] : 0.0f;
        #pragma unroll
        for (int o = 4; o; o >>= 1) x += __shfl_xor_sync(0xffffffffu, x, o);
        if (t == 0) red[0] = x;
    }
    __syncthreads();
    const float inv = 1.0f / red[0];

    v.x *= inv; v.y *= inv; v.z *= inv; v.w *= inv;
    p[t] = v;
}

// ============================================================================
// launch
// ============================================================================
extern "C" void kernel_launch(void* const* d_in, const int* in_sizes, int n_in,
                              void* d_out, int out_size)
{
    const float* node  = (const float*)d_in[0];
    const float* hyper = (const float*)d_in[1];
    const float* Wq    = (const float*)d_in[2];
    const float* bq    = (const float*)d_in[3];
    const float* Wkv   = (const float*)d_in[4];
    const float* bkv   = (const float*)d_in[5];
    float* out = (float*)d_out;

    float *pQ, *pKV, *pVt, *pS;
    cudaGetSymbolAddress((void**)&pQ,  g_Q);
    cudaGetSymbolAddress((void**)&pKV, g_KV);
    cudaGetSymbolAddress((void**)&pVt, g_Vt);
    cudaGetSymbolAddress((void**)&pS,  g_S);

    const float scale = 0.04419417382415922f;  // 512^-0.5

    // 1) Q = node @ Wq^T + bq           (M=32768, N=512, K=512)
    tc_gemm<<<dim3(CC / 128, (BATCH * NN) / 128, 1), 512>>>(
        node, Wq, bq, pQ, CC, CC, CC, CC, 0, 0, 0, 1.0f);

    // 2) KV = hyper @ Wkv^T + bkv       (M=8192, N=1024, K=512)
    tc_gemm<<<dim3((2 * CC) / 128, (BATCH * EE) / 128, 1), 512>>>(
        hyper, Wkv, bkv, pKV, CC, CC, CC, 2 * CC, 0, 0, 0, 1.0f);

    // 3) Vt[b][c][e] = V[b][e][c]
    transpose_v<<<dim3(EE / 32, CC / 32, BATCH), dim3(32, 8)>>>(pKV, pVt);

    // 4) S = scale * Q @ K^T   (batched; K rows = first CC cols of KV, ldb=2C)
    tc_gemm<<<dim3(EE / 128, NN / 128, BATCH), 512>>>(
        pQ, pKV, nullptr, pS,
        CC, CC, 2 * CC, EE,
        (size_t)NN * CC, (size_t)EE * 2 * CC, (size_t)NN * EE, scale);

    // 5) softmax rows
    softmax_rows<<<BATCH * NN, 256>>>(pS);

    // 6) out = P @ Vt^T        (batched; M=4096, N=512, K=1024)
    tc_gemm<<<dim3(CC / 128, NN / 128, BATCH), 512>>>(
        pS, pVt, nullptr, out,
        EE, EE, EE, CC,
        (size_t)NN * EE, (size_t)CC * EE, (size_t)NN * CC, 1.0f);
}

// round 13
// speedup vs baseline: 2.4117x; 1.2140x over previous
#include <cuda_runtime.h>
#include <cuda_bf16.h>
#include <math.h>
#include <stdint.h>

#define BATCH 8
#define NN    4096
#define EE    1024
#define CC    512

typedef __nv_bfloat16 bf16;

// ---- scratch (device globals: allocation-free) ----
__device__ bf16  g_Nhi [(size_t)BATCH * NN * CC];
__device__ bf16  g_Nlo [(size_t)BATCH * NN * CC];
__device__ bf16  g_Hhi [(size_t)BATCH * EE * CC];
__device__ bf16  g_Hlo [(size_t)BATCH * EE * CC];
__device__ bf16  g_Wqhi[(size_t)CC * CC];
__device__ bf16  g_Wqlo[(size_t)CC * CC];
__device__ bf16  g_Wkhi[(size_t)2 * CC * CC];
__device__ bf16  g_Wklo[(size_t)2 * CC * CC];
__device__ bf16  g_Qhi [(size_t)BATCH * NN * CC];
__device__ bf16  g_Qlo [(size_t)BATCH * NN * CC];
__device__ bf16  g_KVhi[(size_t)BATCH * EE * 2 * CC];
__device__ bf16  g_KVlo[(size_t)BATCH * EE * 2 * CC];
__device__ bf16  g_Vthi[(size_t)BATCH * CC * EE];
__device__ bf16  g_Vtlo[(size_t)BATCH * CC * EE];
__device__ float g_S   [(size_t)BATCH * NN * EE];      // 128 MB
__device__ bf16  g_Phi [(size_t)BATCH * NN * EE];
__device__ bf16  g_Plo [(size_t)BATCH * NN * EE];

// ============================================================================
// helpers
// ============================================================================
static __device__ __forceinline__ uint32_t smem_u32(const void* p) {
    uint32_t a;
    asm("{ .reg .u64 t; cvta.to.shared.u64 t, %1; cvt.u32.u64 %0, t; }" : "=r"(a) : "l"(p));
    return a;
}
static __device__ __forceinline__ void mma_bf16(float* d, const uint32_t* a, const uint32_t* b) {
    asm volatile(
        "mma.sync.aligned.m16n8k16.row.col.f32.bf16.bf16.f32 "
        "{%0,%1,%2,%3}, {%4,%5,%6,%7}, {%8,%9}, {%0,%1,%2,%3};"
        : "+f"(d[0]), "+f"(d[1]), "+f"(d[2]), "+f"(d[3])
        : "r"(a[0]), "r"(a[1]), "r"(a[2]), "r"(a[3]), "r"(b[0]), "r"(b[1]));
}
static __device__ __forceinline__ void ldsm4(uint32_t* r, uint32_t addr) {
    asm volatile("ldmatrix.sync.aligned.m8n8.x4.shared.b16 {%0,%1,%2,%3}, [%4];"
        : "=r"(r[0]), "=r"(r[1]), "=r"(r[2]), "=r"(r[3]) : "r"(addr));
}
static __device__ __forceinline__ void split2(float x, float y, uint32_t& hi, uint32_t& lo) {
    bf16 hx = __float2bfloat16(x), hy = __float2bfloat16(y);
    __nv_bfloat162 h; h.x = hx; h.y = hy;
    __nv_bfloat162 l;
    l.x = __float2bfloat16(x - __bfloat162float(hx));
    l.y = __float2bfloat16(y - __bfloat162float(hy));
    hi = *reinterpret_cast<uint32_t*>(&h);
    lo = *reinterpret_cast<uint32_t*>(&l);
}

// ============================================================================
// elementwise fp32 -> bf16 hi/lo split (vectorized by 4)
// ============================================================================
__global__ __launch_bounds__(256) void split_f32(
    const float* __restrict__ x, bf16* __restrict__ hi, bf16* __restrict__ lo, int n4)
{
    int t = blockIdx.x * blockDim.x + threadIdx.x;
    if (t >= n4) return;
    float4 v = ((const float4*)x)[t];
    uint2 h, l;
    split2(v.x, v.y, h.x, l.x);
    split2(v.z, v.w, h.y, l.y);
    ((uint2*)hi)[t] = h;
    ((uint2*)lo)[t] = l;
}

// ============================================================================
// Tensor-core NT GEMM, pre-split bf16 hi/lo operands, 3-pass, fp32 acc:
//   C[m,n] = alpha * sum_k A[m,k]*B[n,k] + bias[n]
// Tile 128x128x32, 512 threads (16 warps 4x4, warp tile 32x32).
// 2-stage double-buffered smem. Output: fp32 (Cf) or bf16 hi/lo (Chi/Clo).
// ============================================================================
#define ROWB   80
#define ARR_SZ (128 * ROWB)       // 10240
#define STG_SZ (4 * ARR_SZ)       // 40960
#define SMEM_T (2 * STG_SZ)       // 81920

__global__ __launch_bounds__(512) void tc_gemm_bf(
    const bf16* __restrict__ Ahi, const bf16* __restrict__ Alo,
    const bf16* __restrict__ Bhi, const bf16* __restrict__ Blo,
    const float* __restrict__ bias,
    float* __restrict__ Cf, bf16* __restrict__ Chi, bf16* __restrict__ Clo,
    int K, int lda, int ldb, int ldc,
    size_t sA, size_t sB, size_t sC, float alpha)
{
    extern __shared__ __align__(16) unsigned char sm[];
    const uint32_t sb = smem_u32(sm);

    Ahi += (size_t)blockIdx.z * sA;  Alo += (size_t)blockIdx.z * sA;
    Bhi += (size_t)blockIdx.z * sB;  Blo += (size_t)blockIdx.z * sB;
    // *** THE R4 BUG: C was never offset by the batch stride. Fixed: ***
    if (Cf)  Cf  += (size_t)blockIdx.z * sC;
    if (Chi) Chi += (size_t)blockIdx.z * sC;
    if (Clo) Clo += (size_t)blockIdx.z * sC;

    const int bm = blockIdx.y * 128;
    const int bn = blockIdx.x * 128;

    const int tid  = threadIdx.x;
    const int wid  = tid >> 5;
    const int lane = tid & 31;
    const int warp_m = (wid >> 2) * 32;
    const int warp_n = (wid & 3) * 32;

    // gmem load mapping: 4 threads per 128-row, each thread one uint4 (8 bf16)
    const int lrow = tid >> 2;             // 0..127
    const int lq   = tid & 3;              // 0..3
    const bf16* pAh = Ahi + (size_t)(bm + lrow) * lda + lq * 8;
    const bf16* pAl = Alo + (size_t)(bm + lrow) * lda + lq * 8;
    const bf16* pBh = Bhi + (size_t)(bn + lrow) * ldb + lq * 8;
    const bf16* pBl = Blo + (size_t)(bn + lrow) * ldb + lq * 8;
    const uint32_t st_off = (uint32_t)(lrow * ROWB + lq * 16);

    const uint32_t lm_row  = (uint32_t)(lane & 15);
    const uint32_t lm_koff = (uint32_t)((lane >> 4) * 16);

    float acc[2][4][4];
    #pragma unroll
    for (int i = 0; i < 2; i++)
        #pragma unroll
        for (int j = 0; j < 4; j++)
            #pragma unroll
            for (int q = 0; q < 4; q++) acc[i][j][q] = 0.0f;

    uint4 rah, ral, rbh, rbl;
    auto ldg_chunk = [&](int k0) {
        rah = *(const uint4*)(pAh + k0);
        ral = *(const uint4*)(pAl + k0);
        rbh = *(const uint4*)(pBh + k0);
        rbl = *(const uint4*)(pBl + k0);
    };
    auto sts_chunk = [&](int st) {
        unsigned char* base = sm + st * STG_SZ + st_off;
        *(uint4*)(base + 0 * ARR_SZ) = rah;
        *(uint4*)(base + 1 * ARR_SZ) = ral;
        *(uint4*)(base + 2 * ARR_SZ) = rbh;
        *(uint4*)(base + 3 * ARR_SZ) = rbl;
    };
    auto compute = [&](int st) {
        const uint32_t base = sb + (uint32_t)(st * STG_SZ);
        #pragma unroll
        for (int ks = 0; ks < 2; ks++) {
            const uint32_t kb = (uint32_t)(ks * 32) + lm_koff;
            uint32_t aHi[2][4], aLo[2][4];
            #pragma unroll
            for (int am = 0; am < 2; am++) {
                const uint32_t ro = (uint32_t)(warp_m + am * 16) + lm_row;
                ldsm4(aHi[am], base + 0 * ARR_SZ + ro * ROWB + kb);
                ldsm4(aLo[am], base + 1 * ARR_SZ + ro * ROWB + kb);
            }
            uint32_t bHi[4][2], bLo[4][2];
            #pragma unroll
            for (int bg = 0; bg < 2; bg++) {
                const uint32_t ro = (uint32_t)(warp_n + bg * 16) + lm_row;
                uint32_t r[4];
                ldsm4(r, base + 2 * ARR_SZ + ro * ROWB + kb);
                bHi[bg * 2 + 0][0] = r[0]; bHi[bg * 2 + 0][1] = r[2];
                bHi[bg * 2 + 1][0] = r[1]; bHi[bg * 2 + 1][1] = r[3];
                ldsm4(r, base + 3 * ARR_SZ + ro * ROWB + kb);
                bLo[bg * 2 + 0][0] = r[0]; bLo[bg * 2 + 0][1] = r[2];
                bLo[bg * 2 + 1][0] = r[1]; bLo[bg * 2 + 1][1] = r[3];
            }
            #pragma unroll
            for (int am = 0; am < 2; am++)
                #pragma unroll
                for (int an = 0; an < 4; an++) {
                    mma_bf16(acc[am][an], aHi[am], bHi[an]);
                    mma_bf16(acc[am][an], aHi[am], bLo[an]);
                    mma_bf16(acc[am][an], aLo[am], bHi[an]);
                }
        }
    };

    const int nch = K >> 5;
    ldg_chunk(0);
    sts_chunk(0);
    for (int c = 0; c < nch; c++) {
        __syncthreads();
        if (c + 1 < nch) ldg_chunk((c + 1) << 5);
        compute(c & 1);
        if (c + 1 < nch) sts_chunk((c + 1) & 1);
    }

    // ---- epilogue ----
    const bool hb = (bias != nullptr);
    #pragma unroll
    for (int am = 0; am < 2; am++) {
        #pragma unroll
        for (int an = 0; an < 4; an++) {
            const int col = bn + warp_n + an * 8 + (lane & 3) * 2;
            float bx = 0.f, by = 0.f;
            if (hb) { bx = __ldg(&bias[col]); by = __ldg(&bias[col + 1]); }
            const int r0 = bm + warp_m + am * 16 + (lane >> 2);
            float v0x = acc[am][an][0] * alpha + bx;
            float v0y = acc[am][an][1] * alpha + by;
            float v1x = acc[am][an][2] * alpha + bx;
            float v1y = acc[am][an][3] * alpha + by;
            if (Cf) {
                *(float2*)&Cf[(size_t)r0 * ldc + col]       = make_float2(v0x, v0y);
                *(float2*)&Cf[(size_t)(r0 + 8) * ldc + col] = make_float2(v1x, v1y);
            } else {
                uint32_t h0, l0, h1, l1;
                split2(v0x, v0y, h0, l0);
                split2(v1x, v1y, h1, l1);
                *(uint32_t*)&Chi[(size_t)r0 * ldc + col]       = h0;
                *(uint32_t*)&Clo[(size_t)r0 * ldc + col]       = l0;
                *(uint32_t*)&Chi[(size_t)(r0 + 8) * ldc + col] = h1;
                *(uint32_t*)&Clo[(size_t)(r0 + 8) * ldc + col] = l1;
            }
        }
    }
}

// ============================================================================
// Transpose V half of KV (bf16 hi/lo) into Vt[b][c][e]
// ============================================================================
__global__ void transpose_v_bf(const bf16* __restrict__ KVhi, const bf16* __restrict__ KVlo,
                               bf16* __restrict__ Vthi, bf16* __restrict__ Vtlo)
{
    __shared__ bf16 th[32][33];
    __shared__ bf16 tl[32][33];
    const int b  = blockIdx.z;
    const int e0 = blockIdx.x * 32;
    const int c0 = blockIdx.y * 32;
    const int tx = threadIdx.x;
    const int ty = threadIdx.y;

    #pragma unroll
    for (int i = 0; i < 32; i += 8) {
        size_t idx = ((size_t)b * EE + e0 + ty + i) * (2 * CC) + CC + c0 + tx;
        th[ty + i][tx] = KVhi[idx];
        tl[ty + i][tx] = KVlo[idx];
    }
    __syncthreads();
    #pragma unroll
    for (int i = 0; i < 32; i += 8) {
        size_t idx = ((size_t)b * CC + c0 + ty + i) * EE + e0 + tx;
        Vthi[idx] = th[tx][ty + i];
        Vtlo[idx] = tl[tx][ty + i];
    }
}

// ============================================================================
// Row softmax over E=1024, outputs bf16 hi/lo P.
// ============================================================================
__global__ __launch_bounds__(256) void softmax_rows(
    const float* __restrict__ S, bf16* __restrict__ Phi, bf16* __restrict__ Plo)
{
    __shared__ float red[32];
    const size_t row = blockIdx.x;
    const float4* p = (const float4*)(S + row * (size_t)EE);
    const int t = threadIdx.x;

    float4 v = p[t];

    float m = fmaxf(fmaxf(v.x, v.y), fmaxf(v.z, v.w));
    #pragma unroll
    for (int o = 16; o; o >>= 1) m = fmaxf(m, __shfl_xor_sync(0xffffffffu, m, o));
    if ((t & 31) == 0) red[t >> 5] = m;
    __syncthreads();
    if (t < 32) {
        float x = (t < 8) ? red[t] : -INFINITY;
        #pragma unroll
        for (int o = 4; o; o >>= 1) x = fmaxf(x, __shfl_xor_sync(0xffffffffu, x, o));
        if (t == 0) red[0] = x;
    }
    __syncthreads();
    m = red[0];
    __syncthreads();

    v.x = __expf(v.x - m); v.y = __expf(v.y - m);
    v.z = __expf(v.z - m); v.w = __expf(v.w - m);
    float s = v.x + v.y + v.z + v.w;
    #pragma unroll
    for (int o = 16; o; o >>= 1) s += __shfl_xor_sync(0xffffffffu, s, o);
    if ((t & 31) == 0) red[t >> 5] = s;
    __syncthreads();
    if (t < 32) {
        float x = (t < 8) ? red[t] : 0.0f;
        #pragma unroll
        for (int o = 4; o; o >>= 1) x += __shfl_xor_sync(0xffffffffu, x, o);
        if (t == 0) red[0] = x;
    }
    __syncthreads();
    const float inv = 1.0f / red[0];

    v.x *= inv; v.y *= inv; v.z *= inv; v.w *= inv;
    uint2 h, l;
    split2(v.x, v.y, h.x, l.x);
    split2(v.z, v.w, h.y, l.y);
    ((uint2*)(Phi + row * (size_t)EE))[t] = h;
    ((uint2*)(Plo + row * (size_t)EE))[t] = l;
}

// ============================================================================
// launch
// ============================================================================
extern "C" void kernel_launch(void* const* d_in, const int* in_sizes, int n_in,
                              void* d_out, int out_size)
{
    const float* node  = (const float*)d_in[0];
    const float* hyper = (const float*)d_in[1];
    const float* Wq    = (const float*)d_in[2];
    const float* bq    = (const float*)d_in[3];
    const float* Wkv   = (const float*)d_in[4];
    const float* bkv   = (const float*)d_in[5];
    float* out = (float*)d_out;

    bf16 *pNhi, *pNlo, *pHhi, *pHlo, *pWqhi, *pWqlo, *pWkhi, *pWklo;
    bf16 *pQhi, *pQlo, *pKVhi, *pKVlo, *pVthi, *pVtlo, *pPhi, *pPlo;
    float *pS;
    cudaGetSymbolAddress((void**)&pNhi,  g_Nhi);  cudaGetSymbolAddress((void**)&pNlo,  g_Nlo);
    cudaGetSymbolAddress((void**)&pHhi,  g_Hhi);  cudaGetSymbolAddress((void**)&pHlo,  g_Hlo);
    cudaGetSymbolAddress((void**)&pWqhi, g_Wqhi); cudaGetSymbolAddress((void**)&pWqlo, g_Wqlo);
    cudaGetSymbolAddress((void**)&pWkhi, g_Wkhi); cudaGetSymbolAddress((void**)&pWklo, g_Wklo);
    cudaGetSymbolAddress((void**)&pQhi,  g_Qhi);  cudaGetSymbolAddress((void**)&pQlo,  g_Qlo);
    cudaGetSymbolAddress((void**)&pKVhi, g_KVhi); cudaGetSymbolAddress((void**)&pKVlo, g_KVlo);
    cudaGetSymbolAddress((void**)&pVthi, g_Vthi); cudaGetSymbolAddress((void**)&pVtlo, g_Vtlo);
    cudaGetSymbolAddress((void**)&pPhi,  g_Phi);  cudaGetSymbolAddress((void**)&pPlo,  g_Plo);
    cudaGetSymbolAddress((void**)&pS,    g_S);

    cudaFuncSetAttribute(tc_gemm_bf, cudaFuncAttributeMaxDynamicSharedMemorySize, SMEM_T);

    const float scale = 0.04419417382415922f;  // 512^-0.5

    // 0) pre-split inputs to bf16 hi/lo
    {
        int n4;
        n4 = (BATCH * NN * CC) / 4;
        split_f32<<<(n4 + 255) / 256, 256>>>(node, pNhi, pNlo, n4);
        n4 = (BATCH * EE * CC) / 4;
        split_f32<<<(n4 + 255) / 256, 256>>>(hyper, pHhi, pHlo, n4);
        n4 = (CC * CC) / 4;
        split_f32<<<(n4 + 255) / 256, 256>>>(Wq, pWqhi, pWqlo, n4);
        n4 = (2 * CC * CC) / 4;
        split_f32<<<(n4 + 255) / 256, 256>>>(Wkv, pWkhi, pWklo, n4);
    }

    // 1) Q = node @ Wq^T + bq  -> bf16 hi/lo   (M=32768, N=512, K=512)
    tc_gemm_bf<<<dim3(CC / 128, (BATCH * NN) / 128, 1), 512, SMEM_T>>>(
        pNhi, pNlo, pWqhi, pWqlo, bq, nullptr, pQhi, pQlo,
        CC, CC, CC, CC, 0, 0, 0, 1.0f);

    // 2) KV = hyper @ Wkv^T + bkv -> bf16 hi/lo (M=8192, N=1024, K=512)
    tc_gemm_bf<<<dim3((2 * CC) / 128, (BATCH * EE) / 128, 1), 512, SMEM_T>>>(
        pHhi, pHlo, pWkhi, pWklo, bkv, nullptr, pKVhi, pKVlo,
        CC, CC, CC, 2 * CC, 0, 0, 0, 1.0f);

    // 3) Vt[b][c][e] = V[b][e][c]  (bf16 hi/lo)
    transpose_v_bf<<<dim3(EE / 32, CC / 32, BATCH), dim3(32, 8)>>>(pKVhi, pKVlo, pVthi, pVtlo);

    // 4) S = scale * Q @ K^T  -> fp32  (batched; K = first CC cols of KV, ldb=2C)
    tc_gemm_bf<<<dim3(EE / 128, NN / 128, BATCH), 512, SMEM_T>>>(
        pQhi, pQlo, pKVhi, pKVlo, nullptr, pS, nullptr, nullptr,
        CC, CC, 2 * CC, EE,
        (size_t)NN * CC, (size_t)EE * 2 * CC, (size_t)NN * EE, scale);

    // 5) softmax rows -> bf16 hi/lo P
    softmax_rows<<<BATCH * NN, 256>>>(pS, pPhi, pPlo);

    // 6) out = P @ Vt^T -> fp32  (batched; M=4096, N=512, K=1024)
    tc_gemm_bf<<<dim3(CC / 128, NN / 128, BATCH), 512, SMEM_T>>>(
        pPhi, pPlo, pVthi, pVtlo, nullptr, out, nullptr, nullptr,
        EE, EE, EE, CC,
        (size_t)NN * EE, (size_t)CC * EE, (size_t)NN * CC, 1.0f);
}